// round 1
// baseline (speedup 1.0000x reference)
#include <cuda_runtime.h>

// ---------------- problem constants ----------------
#define BB 128
#define NN 64
#define TT 20
#define FD 2
#define EE 16
#define HH 32
#define AA 32
#define GG 128   // 4*H

// scratch for precomputed normalized attention weights: [B][T][N][N]
__device__ float g_wnorm[BB * TT * NN * NN];

__device__ __forceinline__ float fsig(float x)  { return 1.0f / (1.0f + __expf(-x)); }
__device__ __forceinline__ float ftanh_(float x){ return 2.0f / (1.0f + __expf(-2.0f * x)) - 1.0f; }

// =====================================================================
// Kernel A: precompute normalized spatial attention weights for all (b,t)
// grid = (T, B), 256 threads. thread: row i = tid>>2, quarter q = tid&3.
// =====================================================================
__global__ void __launch_bounds__(256) wnorm_kernel(
    const float* __restrict__ dmat, const float* __restrict__ bmat,
    const float* __restrict__ hmat, const float* __restrict__ mask,
    const float* __restrict__ domain)
{
    __shared__ float sdom[144];
    __shared__ float smk[NN];
    const int tt = blockIdx.x;
    const int b  = blockIdx.y;
    const int tid = threadIdx.x;
    if (tid < 144) sdom[tid] = domain[tid];
    if (tid < NN)  smk[tid]  = mask[(b * NN + tid) * TT + tt];
    __syncthreads();

    const int i = tid >> 2;
    const int q = tid & 3;
    const float mki = smk[i];
    const int base_in  = ((b * NN + i) * TT + tt) * NN + q * 16;
    const int base_out = ((b * TT + tt) * NN + i) * NN + q * 16;

    float wv[16];
    float psum = 0.0f;
#pragma unroll
    for (int u = 0; u < 4; u++) {
        float4 d4 = *(const float4*)(dmat + base_in + 4 * u);
        float4 b4 = *(const float4*)(bmat + base_in + 4 * u);
        float4 h4 = *(const float4*)(hmat + base_in + 4 * u);
        float dv[4] = {d4.x, d4.y, d4.z, d4.w};
        float bv[4] = {b4.x, b4.y, b4.z, b4.w};
        float hv[4] = {h4.x, h4.y, h4.z, h4.w};
#pragma unroll
        for (int v = 0; v < 4; v++) {
            int j = q * 16 + 4 * u + v;
            int ib = (int)floorf(bv[v] / 30.0f);
            int ih = (int)floorf(hv[v] / 30.0f);
            ib = ib < 0 ? 0 : (ib > 11 ? 11 : ib);
            ih = ih < 0 ? 0 : (ih > 11 ? 11 : ih);
            float val = sdom[ib * 12 + ih] - dv[v];
            val = val > 0.0f ? val : 0.0f;
            val *= mki * smk[j];
            if (j == i) val = 0.0f;
            wv[4 * u + v] = val;
            psum += val;
        }
    }
    // reduce row-sum across the 4 lanes of this row (lanes are 4-aligned groups)
    psum += __shfl_xor_sync(0xffffffffu, psum, 1);
    psum += __shfl_xor_sync(0xffffffffu, psum, 2);
    const float inv = 1.0f / (psum + 1e-12f);
#pragma unroll
    for (int u = 0; u < 4; u++) {
        float4 o;
        o.x = wv[4 * u + 0] * inv;
        o.y = wv[4 * u + 1] * inv;
        o.z = wv[4 * u + 2] * inv;
        o.w = wv[4 * u + 3] * inv;
        *(float4*)(g_wnorm + base_out + 4 * u) = o;
    }
}

// =====================================================================
// Kernel B: the sequential per-batch model. 1 CTA per batch, 256 threads.
// warp w owns agents 8w..8w+7; lane l = output dim (0..31).
// All recurrent state in SMEM/registers. One __syncthreads per step.
// =====================================================================

// shared-memory layout (float offsets)
#define OFF_H    0        // [64][32]
#define OFF_HL   2048     // [64][32]
#define OFF_A    4096     // 2 x [64][32] (double-buffered)
#define OFF_ATT  8192     // [64][32]
#define OFF_Z    10240    // [64][32]
#define OFF_W    12288    // [8 warps][8 rows][64] attention weights
#define OFF_WHP  16384    // W_hh staged k4-major: float4[8][128]
#define OFF_E2A  20480    // enc2att k4-major: float4[8][32]
#define OFF_SPA  21504    // spa_W  k4-major: float4[16][32]
#define OFF_A2E  23552    // att2enc k4-major: float4[8][32]
#define OFF_WC   24576    // combined x->gate weights: float2[128]
#define OFF_BC   24832    // combined gate bias: [128]
#define OFF_E2AB 24960    // [32]
#define OFF_SPAB 24992    // [32]
#define OFF_A2EB 25024    // [32]
#define OFF_X    25056    // [64][20][2]
#define SMEM_FLOATS 27616
#define SMEM_BYTES  (SMEM_FLOATS * 4)

__global__ void __launch_bounds__(256, 1) traj_kernel(
    const float* __restrict__ x,
    const float* __restrict__ emb_W,  const float* __restrict__ emb_b,
    const float* __restrict__ W_ih,   const float* __restrict__ W_hh,
    const float* __restrict__ b_ih,   const float* __restrict__ b_hh,
    const float* __restrict__ e2aW,   const float* __restrict__ e2ab,
    const float* __restrict__ spaW,   const float* __restrict__ spab,
    const float* __restrict__ a2eW,   const float* __restrict__ a2eb,
    const float* __restrict__ clsW,   const float* __restrict__ clsb,
    const float* __restrict__ h0,     const float* __restrict__ c0,
    float* __restrict__ out)
{
    extern __shared__ float sm[];
    const int b   = blockIdx.x;
    const int tid = threadIdx.x;
    const int w   = tid >> 5;
    const int l   = tid & 31;

    float*  sh_h    = sm + OFF_H;
    float*  sh_hl   = sm + OFF_HL;
    float*  sh_a    = sm + OFF_A;
    float*  sh_att  = sm + OFF_ATT;
    float*  sh_z    = sm + OFF_Z;
    float*  sh_x    = sm + OFF_X;
    float4* sh_h4   = (float4*)(sm + OFF_H);
    float4* sh_hl4  = (float4*)(sm + OFF_HL);
    float4* sh_a4   = (float4*)(sm + OFF_A);
    float4* sh_att4 = (float4*)(sm + OFF_ATT);
    float4* sh_z4   = (float4*)(sm + OFF_Z);
    float4* shw4    = (float4*)(sm + OFF_W);
    float4* whp4    = (float4*)(sm + OFF_WHP);
    float4* e2a4    = (float4*)(sm + OFF_E2A);
    float4* spa4    = (float4*)(sm + OFF_SPA);
    float4* a2e4    = (float4*)(sm + OFF_A2E);
    float2* wc2     = (float2*)(sm + OFF_WC);
    float*  bcA     = sm + OFF_BC;

    // ---------- prologue: stage weights & per-batch inputs ----------
    // W_hh -> k4-major float4 [k4][128]
    for (int idx = tid; idx < 1024; idx += 256) {
        int g = idx >> 3, k4 = idx & 7;
        whp4[k4 * 128 + g] = ((const float4*)W_hh)[g * 8 + k4];
    }
    // enc2att_W [32][32]
    for (int idx = tid; idx < 256; idx += 256) {
        int d = idx >> 3, k4 = idx & 7;
        e2a4[k4 * 32 + d] = ((const float4*)e2aW)[d * 8 + k4];
    }
    // spa_W [32][64]
    for (int idx = tid; idx < 512; idx += 256) {
        int d = idx >> 4, k4 = idx & 15;
        spa4[k4 * 32 + d] = ((const float4*)spaW)[d * 16 + k4];
    }
    // att2enc_W [32][32]
    for (int idx = tid; idx < 256; idx += 256) {
        int d = idx >> 3, k4 = idx & 7;
        a2e4[k4 * 32 + d] = ((const float4*)a2eW)[d * 8 + k4];
    }
    // combined x-path: Wc = W_ih @ emb_W  (128x2),  bc = W_ih@emb_b + b_ih + b_hh
    if (tid < 128) {
        float wc0 = 0.f, wc1 = 0.f, bcv = 0.f;
#pragma unroll
        for (int e = 0; e < EE; e++) {
            float we = W_ih[tid * EE + e];
            wc0 += we * emb_W[2 * e + 0];
            wc1 += we * emb_W[2 * e + 1];
            bcv += we * emb_b[e];
        }
        wc2[tid] = make_float2(wc0, wc1);
        bcA[tid] = bcv + b_ih[tid] + b_hh[tid];
    }
    if (tid < 32) {
        sm[OFF_E2AB + tid] = e2ab[tid];
        sm[OFF_SPAB + tid] = spab[tid];
        sm[OFF_A2EB + tid] = a2eb[tid];
    }
    // x for this batch: [64][20][2] contiguous
    for (int idx = tid; idx < 640; idx += 256)
        ((float4*)sh_x)[idx] = ((const float4*)(x + (long)b * (NN * TT * FD)))[idx];
    // h init
    for (int idx = tid; idx < 512; idx += 256)
        sh_h4[idx] = ((const float4*)(h0 + (long)b * (NN * HH)))[idx];
    __syncthreads();

    // c state in registers: thread owns (agent 8w+a, dim l)
    float creg[8];
#pragma unroll
    for (int a = 0; a < 8; a++)
        creg[a] = c0[(b * NN + 8 * w + a) * HH + l];

    // hoisted loop-invariant gate constants
    const float2 wci = wc2[l],      wcf = wc2[32 + l];
    const float2 wcg = wc2[64 + l], wco = wc2[96 + l];
    const float bci = bcA[l], bcf = bcA[32 + l], bcg = bcA[64 + l], bco = bcA[96 + l];
    const float e2abr = sm[OFF_E2AB + l];
    const float spabr = sm[OFF_SPAB + l];
    const float a2ebr = sm[OFF_A2EB + l];

    int buf = 0;

    for (int t = 0; t < TT; t++) {
        // ---- prefetch this warp's 8 attention-weight rows (hidden under S1/S2) ----
        const float4* wsrc = (const float4*)(g_wnorm + ((long)b * TT + t) * (NN * NN) + w * 512);
        float4 wr0 = wsrc[l], wr1 = wsrc[l + 32], wr2 = wsrc[l + 64], wr3 = wsrc[l + 96];

        // ================= S1: LSTM gates + cell update =================
#pragma unroll
        for (int gi = 0; gi < 2; gi++) {
            float accI[4] = {0, 0, 0, 0}, accF[4] = {0, 0, 0, 0};
            float accG[4] = {0, 0, 0, 0}, accO[4] = {0, 0, 0, 0};
#pragma unroll
            for (int k4 = 0; k4 < 8; k4++) {
                float4 wiv = whp4[k4 * 128 + l];
                float4 wfv = whp4[k4 * 128 + 32 + l];
                float4 wgv = whp4[k4 * 128 + 64 + l];
                float4 wov = whp4[k4 * 128 + 96 + l];
#pragma unroll
                for (int a = 0; a < 4; a++) {
                    int n = 8 * w + 4 * gi + a;
                    float4 hv = sh_h4[n * 8 + k4];
                    accI[a] += hv.x * wiv.x + hv.y * wiv.y + hv.z * wiv.z + hv.w * wiv.w;
                    accF[a] += hv.x * wfv.x + hv.y * wfv.y + hv.z * wfv.z + hv.w * wfv.w;
                    accG[a] += hv.x * wgv.x + hv.y * wgv.y + hv.z * wgv.z + hv.w * wgv.w;
                    accO[a] += hv.x * wov.x + hv.y * wov.y + hv.z * wov.z + hv.w * wov.w;
                }
            }
#pragma unroll
            for (int a = 0; a < 4; a++) {
                int n = 8 * w + 4 * gi + a;
                int ci = 4 * gi + a;
                float x0 = sh_x[n * (TT * FD) + 2 * t];
                float x1 = sh_x[n * (TT * FD) + 2 * t + 1];
                float gI = accI[a] + x0 * wci.x + x1 * wci.y + bci;
                float gF = accF[a] + x0 * wcf.x + x1 * wcf.y + bcf;
                float gG = accG[a] + x0 * wcg.x + x1 * wcg.y + bcg;
                float gO = accO[a] + x0 * wco.x + x1 * wco.y + bco;
                float cn = fsig(gF) * creg[ci] + fsig(gI) * ftanh_(gG);
                creg[ci] = cn;
                sh_hl[n * HH + l] = fsig(gO) * ftanh_(cn);
            }
        }
        __syncwarp();

        // ================= S2: a = hl @ enc2att_W^T + b =================
#pragma unroll
        for (int gi = 0; gi < 2; gi++) {
            float acc[4] = {e2abr, e2abr, e2abr, e2abr};
#pragma unroll
            for (int k4 = 0; k4 < 8; k4++) {
                float4 wv = e2a4[k4 * 32 + l];
#pragma unroll
                for (int a = 0; a < 4; a++) {
                    float4 hv = sh_hl4[(8 * w + 4 * gi + a) * 8 + k4];
                    acc[a] += hv.x * wv.x + hv.y * wv.y + hv.z * wv.z + hv.w * wv.w;
                }
            }
#pragma unroll
            for (int a = 0; a < 4; a++)
                sh_a[buf * 2048 + (8 * w + 4 * gi + a) * HH + l] = acc[a];
        }
        __syncthreads();   // publish sh_a[buf] to all warps (only block barrier per step)

        // ================= S3: att = w @ a (rows are warp-private) =================
        shw4[w * 128 + l]      = wr0;
        shw4[w * 128 + 32 + l] = wr1;
        shw4[w * 128 + 64 + l] = wr2;
        shw4[w * 128 + 96 + l] = wr3;
        __syncwarp();
#pragma unroll
        for (int gi = 0; gi < 2; gi++) {
            float acc[4] = {0, 0, 0, 0};
#pragma unroll
            for (int j4 = 0; j4 < 16; j4++) {
                float av0 = sh_a[buf * 2048 + (4 * j4 + 0) * HH + l];
                float av1 = sh_a[buf * 2048 + (4 * j4 + 1) * HH + l];
                float av2 = sh_a[buf * 2048 + (4 * j4 + 2) * HH + l];
                float av3 = sh_a[buf * 2048 + (4 * j4 + 3) * HH + l];
#pragma unroll
                for (int a = 0; a < 4; a++) {
                    float4 wv = shw4[w * 128 + (4 * gi + a) * 16 + j4];
                    acc[a] += wv.x * av0 + wv.y * av1 + wv.z * av2 + wv.w * av3;
                }
            }
#pragma unroll
            for (int a = 0; a < 4; a++)
                sh_att[(8 * w + 4 * gi + a) * HH + l] = acc[a];
        }
        __syncwarp();

        // ================= S4: z = tanh([a,att] @ spa_W^T + b) =================
#pragma unroll
        for (int gi = 0; gi < 2; gi++) {
            float acc[4] = {spabr, spabr, spabr, spabr};
#pragma unroll
            for (int k4 = 0; k4 < 8; k4++) {
                float4 wv = spa4[k4 * 32 + l];
#pragma unroll
                for (int a = 0; a < 4; a++) {
                    float4 av = sh_a4[buf * 512 + (8 * w + 4 * gi + a) * 8 + k4];
                    acc[a] += av.x * wv.x + av.y * wv.y + av.z * wv.z + av.w * wv.w;
                }
            }
#pragma unroll
            for (int k4 = 0; k4 < 8; k4++) {
                float4 wv = spa4[(8 + k4) * 32 + l];
#pragma unroll
                for (int a = 0; a < 4; a++) {
                    float4 tv = sh_att4[(8 * w + 4 * gi + a) * 8 + k4];
                    acc[a] += tv.x * wv.x + tv.y * wv.y + tv.z * wv.z + tv.w * wv.w;
                }
            }
#pragma unroll
            for (int a = 0; a < 4; a++)
                sh_z[(8 * w + 4 * gi + a) * HH + l] = ftanh_(acc[a]);
        }
        __syncwarp();

        // ================= S5: h = z @ att2enc_W^T + b =================
#pragma unroll
        for (int gi = 0; gi < 2; gi++) {
            float acc[4] = {a2ebr, a2ebr, a2ebr, a2ebr};
#pragma unroll
            for (int k4 = 0; k4 < 8; k4++) {
                float4 wv = a2e4[k4 * 32 + l];
#pragma unroll
                for (int a = 0; a < 4; a++) {
                    float4 zv = sh_z4[(8 * w + 4 * gi + a) * 8 + k4];
                    acc[a] += zv.x * wv.x + zv.y * wv.y + zv.z * wv.z + zv.w * wv.w;
                }
            }
#pragma unroll
            for (int a = 0; a < 4; a++)
                sh_h[(8 * w + 4 * gi + a) * HH + l] = acc[a];
        }
        __syncwarp();
        buf ^= 1;
    }

    // ================= classification: sigmoid(tanh(h @ cls_W^T + b)) =================
    const float cw  = clsW[l];
    const float cb0 = clsb[0];
#pragma unroll
    for (int a = 0; a < 8; a++) {
        int n = 8 * w + a;
        float v = sh_h[n * HH + l] * cw;
        v += __shfl_xor_sync(0xffffffffu, v, 16);
        v += __shfl_xor_sync(0xffffffffu, v, 8);
        v += __shfl_xor_sync(0xffffffffu, v, 4);
        v += __shfl_xor_sync(0xffffffffu, v, 2);
        v += __shfl_xor_sync(0xffffffffu, v, 1);
        if (l == 0) out[b * NN + n] = fsig(ftanh_(v + cb0));
    }
}

// =====================================================================
extern "C" void kernel_launch(void* const* d_in, const int* in_sizes, int n_in,
                              void* d_out, int out_size)
{
    const float* x      = (const float*)d_in[0];
    const float* dmat   = (const float*)d_in[1];
    const float* bmat   = (const float*)d_in[2];
    const float* hmat   = (const float*)d_in[3];
    const float* mask   = (const float*)d_in[4];
    const float* emb_W  = (const float*)d_in[5];
    const float* emb_b  = (const float*)d_in[6];
    const float* W_ih   = (const float*)d_in[7];
    const float* W_hh   = (const float*)d_in[8];
    const float* b_ih   = (const float*)d_in[9];
    const float* b_hh   = (const float*)d_in[10];
    const float* domain = (const float*)d_in[11];
    const float* e2aW   = (const float*)d_in[12];
    const float* e2ab   = (const float*)d_in[13];
    const float* spaW   = (const float*)d_in[14];
    const float* spab   = (const float*)d_in[15];
    const float* a2eW   = (const float*)d_in[16];
    const float* a2eb   = (const float*)d_in[17];
    const float* clsW   = (const float*)d_in[18];
    const float* clsb   = (const float*)d_in[19];
    const float* h0     = (const float*)d_in[20];
    const float* c0     = (const float*)d_in[21];
    float* out = (float*)d_out;

    static bool attr_set = false;
    // idempotent attribute set (host-side state, not a stream op)
    cudaFuncSetAttribute(traj_kernel, cudaFuncAttributeMaxDynamicSharedMemorySize, SMEM_BYTES);

    dim3 gA(TT, BB);
    wnorm_kernel<<<gA, 256>>>(dmat, bmat, hmat, mask, domain);
    traj_kernel<<<BB, 256, SMEM_BYTES>>>(x, emb_W, emb_b, W_ih, W_hh, b_ih, b_hh,
                                         e2aW, e2ab, spaW, spab, a2eW, a2eb,
                                         clsW, clsb, h0, c0, out);
    (void)attr_set; (void)in_sizes; (void)n_in; (void)out_size;
}

// round 4
// speedup vs baseline: 1.1161x; 1.1161x over previous
#include <cuda_runtime.h>

// ---------------- problem constants ----------------
#define BB 128
#define NN 64
#define TT 20
#define FD 2
#define EE 16
#define HH 32
#define AA 32

// scratch for precomputed normalized attention weights: [B][T][N][N]
__device__ float g_wnorm[BB * TT * NN * NN];

__device__ __forceinline__ float fsig(float x)  { return 1.0f / (1.0f + __expf(-x)); }
__device__ __forceinline__ float ftanh_(float x){ return 2.0f / (1.0f + __expf(-2.0f * x)) - 1.0f; }

// =====================================================================
// Kernel A: precompute normalized spatial attention weights for all (b,t)
// (unchanged from R0 — memory-bound, near roofline)
// =====================================================================
__global__ void __launch_bounds__(256) wnorm_kernel(
    const float* __restrict__ dmat, const float* __restrict__ bmat,
    const float* __restrict__ hmat, const float* __restrict__ mask,
    const float* __restrict__ domain)
{
    __shared__ float sdom[144];
    __shared__ float smk[NN];
    const int tt = blockIdx.x;
    const int b  = blockIdx.y;
    const int tid = threadIdx.x;
    if (tid < 144) sdom[tid] = domain[tid];
    if (tid < NN)  smk[tid]  = mask[(b * NN + tid) * TT + tt];
    __syncthreads();

    const int i = tid >> 2;
    const int q = tid & 3;
    const float mki = smk[i];
    const int base_in  = ((b * NN + i) * TT + tt) * NN + q * 16;
    const int base_out = ((b * TT + tt) * NN + i) * NN + q * 16;

    float wv[16];
    float psum = 0.0f;
#pragma unroll
    for (int u = 0; u < 4; u++) {
        float4 d4 = *(const float4*)(dmat + base_in + 4 * u);
        float4 b4 = *(const float4*)(bmat + base_in + 4 * u);
        float4 h4 = *(const float4*)(hmat + base_in + 4 * u);
        float dv[4] = {d4.x, d4.y, d4.z, d4.w};
        float bv[4] = {b4.x, b4.y, b4.z, b4.w};
        float hv[4] = {h4.x, h4.y, h4.z, h4.w};
#pragma unroll
        for (int v = 0; v < 4; v++) {
            int j = q * 16 + 4 * u + v;
            int ib = (int)floorf(bv[v] / 30.0f);
            int ih = (int)floorf(hv[v] / 30.0f);
            ib = ib < 0 ? 0 : (ib > 11 ? 11 : ib);
            ih = ih < 0 ? 0 : (ih > 11 ? 11 : ih);
            float val = sdom[ib * 12 + ih] - dv[v];
            val = val > 0.0f ? val : 0.0f;
            val *= mki * smk[j];
            if (j == i) val = 0.0f;
            wv[4 * u + v] = val;
            psum += val;
        }
    }
    psum += __shfl_xor_sync(0xffffffffu, psum, 1);
    psum += __shfl_xor_sync(0xffffffffu, psum, 2);
    const float inv = 1.0f / (psum + 1e-12f);
#pragma unroll
    for (int u = 0; u < 4; u++) {
        float4 o;
        o.x = wv[4 * u + 0] * inv;
        o.y = wv[4 * u + 1] * inv;
        o.z = wv[4 * u + 2] * inv;
        o.w = wv[4 * u + 3] * inv;
        *(float4*)(g_wnorm + base_out + 4 * u) = o;
    }
}

// =====================================================================
// Kernel B: sequential per-batch model. 1 CTA per batch, 512 threads.
// warp w (0..15) owns agents 4w..4w+3; lane l = output dim (0..31).
// Same structure as the passing R0 kernel (scalar FFMA, register
// prefetch of attention tiles) — only the occupancy is doubled.
// =====================================================================

// shared-memory layout (float offsets)
#define OFF_H    0        // [64][32]
#define OFF_HL   2048     // [64][32]
#define OFF_A    4096     // 2 x [64][32] (double-buffered)
#define OFF_ATT  8192     // [64][32]
#define OFF_Z    10240    // [64][32]
#define OFF_W    12288    // [16 warps][4 rows][64] attention weights (warp-private)
#define OFF_WH   16384    // W_hh staged k4-major: float4[8][128]
#define OFF_E2A  20480    // enc2att k4-major: float4[8][32]
#define OFF_SPA  21504    // spa_W  k4-major: float4[16][32]
#define OFF_A2E  23552    // att2enc k4-major: float4[8][32]
#define OFF_WC   24576    // combined x->gate weights: float2[128]
#define OFF_BC   24832    // combined gate bias: [128]
#define OFF_E2AB 24960    // [32]
#define OFF_SPAB 24992    // [32]
#define OFF_A2EB 25024    // [32]
#define OFF_X    25056    // [64][20][2]
#define SMEM_FLOATS 27616
#define SMEM_BYTES  (SMEM_FLOATS * 4)

__global__ void __launch_bounds__(512, 1) traj_kernel(
    const float* __restrict__ x,
    const float* __restrict__ emb_W,  const float* __restrict__ emb_b,
    const float* __restrict__ W_ih,   const float* __restrict__ W_hh,
    const float* __restrict__ b_ih,   const float* __restrict__ b_hh,
    const float* __restrict__ e2aW,   const float* __restrict__ e2ab,
    const float* __restrict__ spaW,   const float* __restrict__ spab,
    const float* __restrict__ a2eW,   const float* __restrict__ a2eb,
    const float* __restrict__ clsW,   const float* __restrict__ clsb,
    const float* __restrict__ h0,     const float* __restrict__ c0,
    float* __restrict__ out)
{
    extern __shared__ float sm[];
    const int b   = blockIdx.x;
    const int tid = threadIdx.x;
    const int w   = tid >> 5;   // 0..15
    const int l   = tid & 31;
    const int n0  = 4 * w;      // first agent of this warp

    float*  sh_h    = sm + OFF_H;
    float*  sh_hl   = sm + OFF_HL;
    float*  sh_a    = sm + OFF_A;
    float*  sh_att  = sm + OFF_ATT;
    float*  sh_z    = sm + OFF_Z;
    float*  sh_x    = sm + OFF_X;
    float4* sh_h4   = (float4*)(sm + OFF_H);
    float4* sh_hl4  = (float4*)(sm + OFF_HL);
    float4* sh_a4   = (float4*)(sm + OFF_A);
    float4* sh_att4 = (float4*)(sm + OFF_ATT);
    float4* sh_z4   = (float4*)(sm + OFF_Z);
    float4* shw4    = (float4*)(sm + OFF_W);
    float4* wh4     = (float4*)(sm + OFF_WH);
    float4* e2a4    = (float4*)(sm + OFF_E2A);
    float4* spa4    = (float4*)(sm + OFF_SPA);
    float4* a2e4    = (float4*)(sm + OFF_A2E);
    float2* wc2     = (float2*)(sm + OFF_WC);
    float*  bcA     = sm + OFF_BC;

    // ---------- prologue: stage weights & per-batch inputs ----------
    for (int idx = tid; idx < 1024; idx += 512) {
        int g = idx >> 3, k4 = idx & 7;
        wh4[k4 * 128 + g] = ((const float4*)W_hh)[g * 8 + k4];
    }
    if (tid < 256) {
        int d = tid >> 3, k4 = tid & 7;
        e2a4[k4 * 32 + d] = ((const float4*)e2aW)[d * 8 + k4];
    }
    {
        int d = tid >> 4, k4 = tid & 15;
        spa4[k4 * 32 + d] = ((const float4*)spaW)[d * 16 + k4];
    }
    if (tid >= 256) {
        int t2 = tid - 256;
        int d = t2 >> 3, k4 = t2 & 7;
        a2e4[k4 * 32 + d] = ((const float4*)a2eW)[d * 8 + k4];
    }
    if (tid < 128) {
        float wc0 = 0.f, wc1 = 0.f, bcv = 0.f;
#pragma unroll
        for (int e = 0; e < EE; e++) {
            float we = W_ih[tid * EE + e];
            wc0 += we * emb_W[2 * e + 0];
            wc1 += we * emb_W[2 * e + 1];
            bcv += we * emb_b[e];
        }
        wc2[tid] = make_float2(wc0, wc1);
        bcA[tid] = bcv + b_ih[tid] + b_hh[tid];
    }
    if (tid >= 128 && tid < 160) {
        int t2 = tid - 128;
        sm[OFF_E2AB + t2] = e2ab[t2];
        sm[OFF_SPAB + t2] = spab[t2];
        sm[OFF_A2EB + t2] = a2eb[t2];
    }
    for (int idx = tid; idx < 640; idx += 512)
        ((float4*)sh_x)[idx] = ((const float4*)(x + (long)b * (NN * TT * FD)))[idx];
    if (tid < 512)
        sh_h4[tid] = ((const float4*)(h0 + (long)b * (NN * HH)))[tid];
    __syncthreads();

    // c state in registers: thread owns (agent 4w+a, dim l)
    float creg[4];
#pragma unroll
    for (int a = 0; a < 4; a++)
        creg[a] = c0[(b * NN + n0 + a) * HH + l];

    // hoisted loop-invariant gate constants
    const float2 wci = wc2[l],      wcf = wc2[32 + l];
    const float2 wcg = wc2[64 + l], wco = wc2[96 + l];
    const float bci = bcA[l], bcf = bcA[32 + l], bcg = bcA[64 + l], bco = bcA[96 + l];
    const float e2abr = sm[OFF_E2AB + l];
    const float spabr = sm[OFF_SPAB + l];
    const float a2ebr = sm[OFF_A2EB + l];

    int buf = 0;

    for (int t = 0; t < TT; t++) {
        // ---- register prefetch of this warp's 4 attention-weight rows ----
        // (global loads issued here, consumed in S3 — latency hidden under S1/S2)
        const float4* wsrc = (const float4*)(g_wnorm + ((long)b * TT + t) * (NN * NN) + w * 256);
        float4 wr0 = wsrc[l], wr1 = wsrc[l + 32];

        // ================= S1: LSTM gates + cell update =================
        {
            float accI[4] = {0, 0, 0, 0}, accF[4] = {0, 0, 0, 0};
            float accG[4] = {0, 0, 0, 0}, accO[4] = {0, 0, 0, 0};
#pragma unroll
            for (int k4 = 0; k4 < 8; k4++) {
                float4 wiv = wh4[k4 * 128 + l];
                float4 wfv = wh4[k4 * 128 + 32 + l];
                float4 wgv = wh4[k4 * 128 + 64 + l];
                float4 wov = wh4[k4 * 128 + 96 + l];
#pragma unroll
                for (int a = 0; a < 4; a++) {
                    float4 hv = sh_h4[(n0 + a) * 8 + k4];
                    accI[a] += hv.x * wiv.x + hv.y * wiv.y + hv.z * wiv.z + hv.w * wiv.w;
                    accF[a] += hv.x * wfv.x + hv.y * wfv.y + hv.z * wfv.z + hv.w * wfv.w;
                    accG[a] += hv.x * wgv.x + hv.y * wgv.y + hv.z * wgv.z + hv.w * wgv.w;
                    accO[a] += hv.x * wov.x + hv.y * wov.y + hv.z * wov.z + hv.w * wov.w;
                }
            }
#pragma unroll
            for (int a = 0; a < 4; a++) {
                int n = n0 + a;
                float x0 = sh_x[n * (TT * FD) + 2 * t];
                float x1 = sh_x[n * (TT * FD) + 2 * t + 1];
                float gI = accI[a] + x0 * wci.x + x1 * wci.y + bci;
                float gF = accF[a] + x0 * wcf.x + x1 * wcf.y + bcf;
                float gG = accG[a] + x0 * wcg.x + x1 * wcg.y + bcg;
                float gO = accO[a] + x0 * wco.x + x1 * wco.y + bco;
                float cn = fsig(gF) * creg[a] + fsig(gI) * ftanh_(gG);
                creg[a] = cn;
                sh_hl[n * HH + l] = fsig(gO) * ftanh_(cn);
            }
        }
        __syncwarp();

        // ================= S2: a = hl @ enc2att_W^T + b =================
        {
            float acc[4] = {e2abr, e2abr, e2abr, e2abr};
#pragma unroll
            for (int k4 = 0; k4 < 8; k4++) {
                float4 wv = e2a4[k4 * 32 + l];
#pragma unroll
                for (int a = 0; a < 4; a++) {
                    float4 hv = sh_hl4[(n0 + a) * 8 + k4];
                    acc[a] += hv.x * wv.x + hv.y * wv.y + hv.z * wv.z + hv.w * wv.w;
                }
            }
#pragma unroll
            for (int a = 0; a < 4; a++)
                sh_a[buf * 2048 + (n0 + a) * HH + l] = acc[a];
        }
        __syncthreads();   // publish sh_a[buf] to all warps (only block barrier per step)

        // ================= S3: att = w @ a (rows are warp-private) =================
        shw4[w * 64 + l]      = wr0;
        shw4[w * 64 + 32 + l] = wr1;
        __syncwarp();
        {
            const float* aB = sh_a + buf * 2048;
            float acc[4] = {0, 0, 0, 0};
#pragma unroll
            for (int j4 = 0; j4 < 16; j4++) {
                float av0 = aB[(4 * j4 + 0) * HH + l];
                float av1 = aB[(4 * j4 + 1) * HH + l];
                float av2 = aB[(4 * j4 + 2) * HH + l];
                float av3 = aB[(4 * j4 + 3) * HH + l];
#pragma unroll
                for (int a = 0; a < 4; a++) {
                    float4 wv = shw4[w * 64 + a * 16 + j4];
                    acc[a] += wv.x * av0 + wv.y * av1 + wv.z * av2 + wv.w * av3;
                }
            }
#pragma unroll
            for (int a = 0; a < 4; a++)
                sh_att[(n0 + a) * HH + l] = acc[a];
        }
        __syncwarp();

        // ================= S4: z = tanh([a,att] @ spa_W^T + b) =================
        {
            float acc[4] = {spabr, spabr, spabr, spabr};
#pragma unroll
            for (int k4 = 0; k4 < 8; k4++) {
                float4 wv = spa4[k4 * 32 + l];
#pragma unroll
                for (int a = 0; a < 4; a++) {
                    float4 av = sh_a4[buf * 512 + (n0 + a) * 8 + k4];
                    acc[a] += av.x * wv.x + av.y * wv.y + av.z * wv.z + av.w * wv.w;
                }
            }
#pragma unroll
            for (int k4 = 0; k4 < 8; k4++) {
                float4 wv = spa4[(8 + k4) * 32 + l];
#pragma unroll
                for (int a = 0; a < 4; a++) {
                    float4 tv = sh_att4[(n0 + a) * 8 + k4];
                    acc[a] += tv.x * wv.x + tv.y * wv.y + tv.z * wv.z + tv.w * wv.w;
                }
            }
#pragma unroll
            for (int a = 0; a < 4; a++)
                sh_z[(n0 + a) * HH + l] = ftanh_(acc[a]);
        }
        __syncwarp();

        // ================= S5: h = z @ att2enc_W^T + b =================
        {
            float acc[4] = {a2ebr, a2ebr, a2ebr, a2ebr};
#pragma unroll
            for (int k4 = 0; k4 < 8; k4++) {
                float4 wv = a2e4[k4 * 32 + l];
#pragma unroll
                for (int a = 0; a < 4; a++) {
                    float4 zv = sh_z4[(n0 + a) * 8 + k4];
                    acc[a] += zv.x * wv.x + zv.y * wv.y + zv.z * wv.z + zv.w * wv.w;
                }
            }
#pragma unroll
            for (int a = 0; a < 4; a++)
                sh_h[(n0 + a) * HH + l] = acc[a];
        }
        __syncwarp();
        buf ^= 1;
    }

    // ================= classification: sigmoid(tanh(h @ cls_W^T + b)) =================
    const float cw  = clsW[l];
    const float cb0 = clsb[0];
#pragma unroll
    for (int a = 0; a < 4; a++) {
        int n = n0 + a;
        float v = sh_h[n * HH + l] * cw;
        v += __shfl_xor_sync(0xffffffffu, v, 16);
        v += __shfl_xor_sync(0xffffffffu, v, 8);
        v += __shfl_xor_sync(0xffffffffu, v, 4);
        v += __shfl_xor_sync(0xffffffffu, v, 2);
        v += __shfl_xor_sync(0xffffffffu, v, 1);
        if (l == 0) out[b * NN + n] = fsig(ftanh_(v + cb0));
    }
}

// =====================================================================
extern "C" void kernel_launch(void* const* d_in, const int* in_sizes, int n_in,
                              void* d_out, int out_size)
{
    const float* x      = (const float*)d_in[0];
    const float* dmat   = (const float*)d_in[1];
    const float* bmat   = (const float*)d_in[2];
    const float* hmat   = (const float*)d_in[3];
    const float* mask   = (const float*)d_in[4];
    const float* emb_W  = (const float*)d_in[5];
    const float* emb_b  = (const float*)d_in[6];
    const float* W_ih   = (const float*)d_in[7];
    const float* W_hh   = (const float*)d_in[8];
    const float* b_ih   = (const float*)d_in[9];
    const float* b_hh   = (const float*)d_in[10];
    const float* domain = (const float*)d_in[11];
    const float* e2aW   = (const float*)d_in[12];
    const float* e2ab   = (const float*)d_in[13];
    const float* spaW   = (const float*)d_in[14];
    const float* spab   = (const float*)d_in[15];
    const float* a2eW   = (const float*)d_in[16];
    const float* a2eb   = (const float*)d_in[17];
    const float* clsW   = (const float*)d_in[18];
    const float* clsb   = (const float*)d_in[19];
    const float* h0     = (const float*)d_in[20];
    const float* c0     = (const float*)d_in[21];
    float* out = (float*)d_out;

    cudaFuncSetAttribute(traj_kernel, cudaFuncAttributeMaxDynamicSharedMemorySize, SMEM_BYTES);

    dim3 gA(TT, BB);
    wnorm_kernel<<<gA, 256>>>(dmat, bmat, hmat, mask, domain);
    traj_kernel<<<BB, 512, SMEM_BYTES>>>(x, emb_W, emb_b, W_ih, W_hh, b_ih, b_hh,
                                         e2aW, e2ab, spaW, spab, a2eW, a2eb,
                                         clsW, clsb, h0, c0, out);
    (void)in_sizes; (void)n_in; (void)out_size;
}

// round 5
// speedup vs baseline: 1.3008x; 1.1654x over previous
#include <cuda_runtime.h>

// ---------------- problem constants ----------------
#define BB 128
#define NN 64
#define TT 20
#define FD 2
#define EE 16
#define HH 32
#define AA 32

// scratch for precomputed normalized attention weights: [B][T][N][N]
__device__ float g_wnorm[BB * TT * NN * NN];

typedef unsigned long long ull;

__device__ __forceinline__ ull ffma2(ull a, ull b, ull c) {
    ull d; asm("fma.rn.f32x2 %0, %1, %2, %3;" : "=l"(d) : "l"(a), "l"(b), "l"(c)); return d;
}
__device__ __forceinline__ ull pk2(float lo, float hi) {
    ull r; asm("mov.b64 %0, {%1, %2};" : "=l"(r) : "f"(lo), "f"(hi)); return r;
}
__device__ __forceinline__ float hadd2(ull v) {
    float lo, hi; asm("mov.b64 {%0, %1}, %2;" : "=f"(lo), "=f"(hi) : "l"(v)); return lo + hi;
}
__device__ __forceinline__ float ftanh_(float x) {
    float r; asm("tanh.approx.f32 %0, %1;" : "=f"(r) : "f"(x)); return r;
}
__device__ __forceinline__ float fsig(float x) {
    return fmaf(0.5f, ftanh_(0.5f * x), 0.5f);
}

// =====================================================================
// Kernel A: precompute normalized spatial attention weights for all (b,t)
// (unchanged — memory-bound, near roofline)
// =====================================================================
__global__ void __launch_bounds__(256) wnorm_kernel(
    const float* __restrict__ dmat, const float* __restrict__ bmat,
    const float* __restrict__ hmat, const float* __restrict__ mask,
    const float* __restrict__ domain)
{
    __shared__ float sdom[144];
    __shared__ float smk[NN];
    const int tt = blockIdx.x;
    const int b  = blockIdx.y;
    const int tid = threadIdx.x;
    if (tid < 144) sdom[tid] = domain[tid];
    if (tid < NN)  smk[tid]  = mask[(b * NN + tid) * TT + tt];
    __syncthreads();

    const int i = tid >> 2;
    const int q = tid & 3;
    const float mki = smk[i];
    const int base_in  = ((b * NN + i) * TT + tt) * NN + q * 16;
    const int base_out = ((b * TT + tt) * NN + i) * NN + q * 16;

    float wv[16];
    float psum = 0.0f;
#pragma unroll
    for (int u = 0; u < 4; u++) {
        float4 d4 = *(const float4*)(dmat + base_in + 4 * u);
        float4 b4 = *(const float4*)(bmat + base_in + 4 * u);
        float4 h4 = *(const float4*)(hmat + base_in + 4 * u);
        float dv[4] = {d4.x, d4.y, d4.z, d4.w};
        float bv[4] = {b4.x, b4.y, b4.z, b4.w};
        float hv[4] = {h4.x, h4.y, h4.z, h4.w};
#pragma unroll
        for (int v = 0; v < 4; v++) {
            int j = q * 16 + 4 * u + v;
            int ib = (int)floorf(bv[v] / 30.0f);
            int ih = (int)floorf(hv[v] / 30.0f);
            ib = ib < 0 ? 0 : (ib > 11 ? 11 : ib);
            ih = ih < 0 ? 0 : (ih > 11 ? 11 : ih);
            float val = sdom[ib * 12 + ih] - dv[v];
            val = val > 0.0f ? val : 0.0f;
            val *= mki * smk[j];
            if (j == i) val = 0.0f;
            wv[4 * u + v] = val;
            psum += val;
        }
    }
    psum += __shfl_xor_sync(0xffffffffu, psum, 1);
    psum += __shfl_xor_sync(0xffffffffu, psum, 2);
    const float inv = 1.0f / (psum + 1e-12f);
#pragma unroll
    for (int u = 0; u < 4; u++) {
        float4 o;
        o.x = wv[4 * u + 0] * inv;
        o.y = wv[4 * u + 1] * inv;
        o.z = wv[4 * u + 2] * inv;
        o.w = wv[4 * u + 3] * inv;
        *(float4*)(g_wnorm + base_out + 4 * u) = o;
    }
}

// =====================================================================
// Kernel B: sequential per-batch model. 1 CTA per batch, 512 threads.
// warp w (0..15) owns agents 4w..4w+3; lane l = output dim (0..31).
// R3 skeleton + fma.rn.f32x2 packed reductions + tanh.approx activations.
// =====================================================================

// shared-memory layout (float offsets)
#define OFF_H    0        // [64][32]
#define OFF_HL   2048     // [64][32]
#define OFF_A    4096     // 2 x [64][32] (double-buffered)
#define OFF_ATT  8192     // [64][32]
#define OFF_Z    10240    // [64][32]
#define OFF_W    12288    // [16 warps][4 rows][64] attention weights (warp-private)
#define OFF_WH   16384    // W_hh staged k4-major: float4[8][128]
#define OFF_E2A  20480    // enc2att k4-major: float4[8][32]
#define OFF_SPA  21504    // spa_W  k4-major: float4[16][32]
#define OFF_A2E  23552    // att2enc k4-major: float4[8][32]
#define OFF_WC   24576    // combined x->gate weights: float2[128]
#define OFF_BC   24832    // combined gate bias: [128]
#define OFF_E2AB 24960    // [32]
#define OFF_SPAB 24992    // [32]
#define OFF_A2EB 25024    // [32]
#define OFF_X    25056    // [64][20][2]
#define SMEM_FLOATS 27616
#define SMEM_BYTES  (SMEM_FLOATS * 4)

__global__ void __launch_bounds__(512, 1) traj_kernel(
    const float* __restrict__ x,
    const float* __restrict__ emb_W,  const float* __restrict__ emb_b,
    const float* __restrict__ W_ih,   const float* __restrict__ W_hh,
    const float* __restrict__ b_ih,   const float* __restrict__ b_hh,
    const float* __restrict__ e2aW,   const float* __restrict__ e2ab,
    const float* __restrict__ spaW,   const float* __restrict__ spab,
    const float* __restrict__ a2eW,   const float* __restrict__ a2eb,
    const float* __restrict__ clsW,   const float* __restrict__ clsb,
    const float* __restrict__ h0,     const float* __restrict__ c0,
    float* __restrict__ out)
{
    extern __shared__ float sm[];
    const int b   = blockIdx.x;
    const int tid = threadIdx.x;
    const int w   = tid >> 5;   // 0..15
    const int l   = tid & 31;
    const int n0  = 4 * w;      // first agent of this warp

    float*  sh_h   = sm + OFF_H;
    float*  sh_hl  = sm + OFF_HL;
    float*  sh_a   = sm + OFF_A;
    float*  sh_att = sm + OFF_ATT;
    float*  sh_z   = sm + OFF_Z;
    float*  sh_x   = sm + OFF_X;
    float4* sh_h4  = (float4*)(sm + OFF_H);
    float4* shw4   = (float4*)(sm + OFF_W);
    float4* wh4f   = (float4*)(sm + OFF_WH);
    float4* e2a4f  = (float4*)(sm + OFF_E2A);
    float4* spa4f  = (float4*)(sm + OFF_SPA);
    float4* a2e4f  = (float4*)(sm + OFF_A2E);
    float2* wc2    = (float2*)(sm + OFF_WC);
    float*  bcA    = sm + OFF_BC;

    // packed-pair views (same memory, read as 2x f32x2)
    const ulonglong2* wh2  = (const ulonglong2*)(sm + OFF_WH);
    const ulonglong2* e2a2 = (const ulonglong2*)(sm + OFF_E2A);
    const ulonglong2* spa2 = (const ulonglong2*)(sm + OFF_SPA);
    const ulonglong2* a2e2 = (const ulonglong2*)(sm + OFF_A2E);
    const ulonglong2* h2p   = (const ulonglong2*)(sm + OFF_H)   + n0 * 8;  // [agent][k4]
    const ulonglong2* hl2p  = (const ulonglong2*)(sm + OFF_HL)  + n0 * 8;
    const ulonglong2* att2p = (const ulonglong2*)(sm + OFF_ATT) + n0 * 8;
    const ulonglong2* z2p   = (const ulonglong2*)(sm + OFF_Z)   + n0 * 8;

    // ---------- prologue: stage weights & per-batch inputs ----------
    for (int idx = tid; idx < 1024; idx += 512) {
        int g = idx >> 3, k4 = idx & 7;
        wh4f[k4 * 128 + g] = ((const float4*)W_hh)[g * 8 + k4];
    }
    if (tid < 256) {
        int d = tid >> 3, k4 = tid & 7;
        e2a4f[k4 * 32 + d] = ((const float4*)e2aW)[d * 8 + k4];
    }
    {
        int d = tid >> 4, k4 = tid & 15;
        spa4f[k4 * 32 + d] = ((const float4*)spaW)[d * 16 + k4];
    }
    if (tid >= 256) {
        int t2 = tid - 256;
        int d = t2 >> 3, k4 = t2 & 7;
        a2e4f[k4 * 32 + d] = ((const float4*)a2eW)[d * 8 + k4];
    }
    if (tid < 128) {
        float wc0 = 0.f, wc1 = 0.f, bcv = 0.f;
#pragma unroll
        for (int e = 0; e < EE; e++) {
            float we = W_ih[tid * EE + e];
            wc0 += we * emb_W[2 * e + 0];
            wc1 += we * emb_W[2 * e + 1];
            bcv += we * emb_b[e];
        }
        wc2[tid] = make_float2(wc0, wc1);
        bcA[tid] = bcv + b_ih[tid] + b_hh[tid];
    }
    if (tid >= 128 && tid < 160) {
        int t2 = tid - 128;
        sm[OFF_E2AB + t2] = e2ab[t2];
        sm[OFF_SPAB + t2] = spab[t2];
        sm[OFF_A2EB + t2] = a2eb[t2];
    }
    for (int idx = tid; idx < 640; idx += 512)
        ((float4*)sh_x)[idx] = ((const float4*)(x + (long)b * (NN * TT * FD)))[idx];
    if (tid < 512)
        sh_h4[tid] = ((const float4*)(h0 + (long)b * (NN * HH)))[tid];
    __syncthreads();

    // c state in registers: thread owns (agent 4w+a, dim l)
    float creg[4];
#pragma unroll
    for (int a = 0; a < 4; a++)
        creg[a] = c0[(b * NN + n0 + a) * HH + l];

    // hoisted loop-invariant gate constants
    const float2 wci = wc2[l],      wcf = wc2[32 + l];
    const float2 wcg = wc2[64 + l], wco = wc2[96 + l];
    const float bci = bcA[l], bcf = bcA[32 + l], bcg = bcA[64 + l], bco = bcA[96 + l];
    const float e2abr = sm[OFF_E2AB + l];
    const float spabr = sm[OFF_SPAB + l];
    const float a2ebr = sm[OFF_A2EB + l];

    int buf = 0;

    for (int t = 0; t < TT; t++) {
        // ---- register prefetch of this warp's 4 attention-weight rows ----
        const float4* wsrc = (const float4*)(g_wnorm + ((long)b * TT + t) * (NN * NN) + w * 256);
        float4 wr0 = wsrc[l], wr1 = wsrc[l + 32];

        // ================= S1: LSTM gates + cell update (packed over k) =========
        {
            ull accI[4] = {0,0,0,0}, accF[4] = {0,0,0,0};
            ull accG[4] = {0,0,0,0}, accO[4] = {0,0,0,0};
#pragma unroll
            for (int k4 = 0; k4 < 8; k4++) {
                ulonglong2 wI = wh2[k4 * 128 + l];
                ulonglong2 wF = wh2[k4 * 128 + 32 + l];
                ulonglong2 wG = wh2[k4 * 128 + 64 + l];
                ulonglong2 wO = wh2[k4 * 128 + 96 + l];
#pragma unroll
                for (int a = 0; a < 4; a++) {
                    ulonglong2 hv = h2p[a * 8 + k4];
                    accI[a] = ffma2(hv.x, wI.x, accI[a]); accI[a] = ffma2(hv.y, wI.y, accI[a]);
                    accF[a] = ffma2(hv.x, wF.x, accF[a]); accF[a] = ffma2(hv.y, wF.y, accF[a]);
                    accG[a] = ffma2(hv.x, wG.x, accG[a]); accG[a] = ffma2(hv.y, wG.y, accG[a]);
                    accO[a] = ffma2(hv.x, wO.x, accO[a]); accO[a] = ffma2(hv.y, wO.y, accO[a]);
                }
            }
#pragma unroll
            for (int a = 0; a < 4; a++) {
                int n = n0 + a;
                float x0 = sh_x[n * (TT * FD) + 2 * t];
                float x1 = sh_x[n * (TT * FD) + 2 * t + 1];
                float gI = hadd2(accI[a]) + x0 * wci.x + x1 * wci.y + bci;
                float gF = hadd2(accF[a]) + x0 * wcf.x + x1 * wcf.y + bcf;
                float gG = hadd2(accG[a]) + x0 * wcg.x + x1 * wcg.y + bcg;
                float gO = hadd2(accO[a]) + x0 * wco.x + x1 * wco.y + bco;
                float cn = fsig(gF) * creg[a] + fsig(gI) * ftanh_(gG);
                creg[a] = cn;
                sh_hl[n * HH + l] = fsig(gO) * ftanh_(cn);
            }
        }
        __syncwarp();

        // ================= S2: a = hl @ enc2att_W^T + b =================
        {
            ull acc[4];
#pragma unroll
            for (int a = 0; a < 4; a++) acc[a] = pk2(e2abr, 0.0f);
#pragma unroll
            for (int k4 = 0; k4 < 8; k4++) {
                ulonglong2 wv = e2a2[k4 * 32 + l];
#pragma unroll
                for (int a = 0; a < 4; a++) {
                    ulonglong2 hv = hl2p[a * 8 + k4];
                    acc[a] = ffma2(hv.x, wv.x, acc[a]);
                    acc[a] = ffma2(hv.y, wv.y, acc[a]);
                }
            }
#pragma unroll
            for (int a = 0; a < 4; a++)
                sh_a[buf * 2048 + (n0 + a) * HH + l] = hadd2(acc[a]);
        }
        __syncthreads();   // publish sh_a[buf] to all warps (only block barrier per step)

        // ================= S3: att = w @ a (rows are warp-private) =================
        shw4[w * 64 + l]      = wr0;
        shw4[w * 64 + 32 + l] = wr1;
        __syncwarp();
        {
            const float* aB = sh_a + buf * 2048;
            const ulonglong2* wp2 = (const ulonglong2*)(shw4 + w * 64);
            ull acc[4] = {0, 0, 0, 0};
#pragma unroll
            for (int j4 = 0; j4 < 16; j4++) {
                float a0 = aB[(4 * j4 + 0) * HH + l];
                float a1 = aB[(4 * j4 + 1) * HH + l];
                float a2 = aB[(4 * j4 + 2) * HH + l];
                float a3 = aB[(4 * j4 + 3) * HH + l];
                ull ap0 = pk2(a0, a1);
                ull ap1 = pk2(a2, a3);
#pragma unroll
                for (int a = 0; a < 4; a++) {
                    ulonglong2 wv = wp2[a * 16 + j4];
                    acc[a] = ffma2(ap0, wv.x, acc[a]);
                    acc[a] = ffma2(ap1, wv.y, acc[a]);
                }
            }
#pragma unroll
            for (int a = 0; a < 4; a++)
                sh_att[(n0 + a) * HH + l] = hadd2(acc[a]);
        }
        __syncwarp();

        // ================= S4: z = tanh([a,att] @ spa_W^T + b) =================
        {
            const ulonglong2* a2p = (const ulonglong2*)(sh_a + buf * 2048) + n0 * 8;
            ull acc[4];
#pragma unroll
            for (int a = 0; a < 4; a++) acc[a] = pk2(spabr, 0.0f);
#pragma unroll
            for (int k4 = 0; k4 < 8; k4++) {
                ulonglong2 wv = spa2[k4 * 32 + l];
#pragma unroll
                for (int a = 0; a < 4; a++) {
                    ulonglong2 av = a2p[a * 8 + k4];
                    acc[a] = ffma2(av.x, wv.x, acc[a]);
                    acc[a] = ffma2(av.y, wv.y, acc[a]);
                }
            }
#pragma unroll
            for (int k4 = 0; k4 < 8; k4++) {
                ulonglong2 wv = spa2[(8 + k4) * 32 + l];
#pragma unroll
                for (int a = 0; a < 4; a++) {
                    ulonglong2 tv = att2p[a * 8 + k4];
                    acc[a] = ffma2(tv.x, wv.x, acc[a]);
                    acc[a] = ffma2(tv.y, wv.y, acc[a]);
                }
            }
#pragma unroll
            for (int a = 0; a < 4; a++)
                sh_z[(n0 + a) * HH + l] = ftanh_(hadd2(acc[a]));
        }
        __syncwarp();

        // ================= S5: h = z @ att2enc_W^T + b =================
        {
            ull acc[4];
#pragma unroll
            for (int a = 0; a < 4; a++) acc[a] = pk2(a2ebr, 0.0f);
#pragma unroll
            for (int k4 = 0; k4 < 8; k4++) {
                ulonglong2 wv = a2e2[k4 * 32 + l];
#pragma unroll
                for (int a = 0; a < 4; a++) {
                    ulonglong2 zv = z2p[a * 8 + k4];
                    acc[a] = ffma2(zv.x, wv.x, acc[a]);
                    acc[a] = ffma2(zv.y, wv.y, acc[a]);
                }
            }
#pragma unroll
            for (int a = 0; a < 4; a++)
                sh_h[(n0 + a) * HH + l] = hadd2(acc[a]);
        }
        __syncwarp();
        buf ^= 1;
    }

    // ================= classification: sigmoid(tanh(h @ cls_W^T + b)) =================
    const float cw  = clsW[l];
    const float cb0 = clsb[0];
#pragma unroll
    for (int a = 0; a < 4; a++) {
        int n = n0 + a;
        float v = sh_h[n * HH + l] * cw;
        v += __shfl_xor_sync(0xffffffffu, v, 16);
        v += __shfl_xor_sync(0xffffffffu, v, 8);
        v += __shfl_xor_sync(0xffffffffu, v, 4);
        v += __shfl_xor_sync(0xffffffffu, v, 2);
        v += __shfl_xor_sync(0xffffffffu, v, 1);
        if (l == 0) out[b * NN + n] = fsig(ftanh_(v + cb0));
    }
}

// =====================================================================
extern "C" void kernel_launch(void* const* d_in, const int* in_sizes, int n_in,
                              void* d_out, int out_size)
{
    const float* x      = (const float*)d_in[0];
    const float* dmat   = (const float*)d_in[1];
    const float* bmat   = (const float*)d_in[2];
    const float* hmat   = (const float*)d_in[3];
    const float* mask   = (const float*)d_in[4];
    const float* emb_W  = (const float*)d_in[5];
    const float* emb_b  = (const float*)d_in[6];
    const float* W_ih   = (const float*)d_in[7];
    const float* W_hh   = (const float*)d_in[8];
    const float* b_ih   = (const float*)d_in[9];
    const float* b_hh   = (const float*)d_in[10];
    const float* domain = (const float*)d_in[11];
    const float* e2aW   = (const float*)d_in[12];
    const float* e2ab   = (const float*)d_in[13];
    const float* spaW   = (const float*)d_in[14];
    const float* spab   = (const float*)d_in[15];
    const float* a2eW   = (const float*)d_in[16];
    const float* a2eb   = (const float*)d_in[17];
    const float* clsW   = (const float*)d_in[18];
    const float* clsb   = (const float*)d_in[19];
    const float* h0     = (const float*)d_in[20];
    const float* c0     = (const float*)d_in[21];
    float* out = (float*)d_out;

    cudaFuncSetAttribute(traj_kernel, cudaFuncAttributeMaxDynamicSharedMemorySize, SMEM_BYTES);

    dim3 gA(TT, BB);
    wnorm_kernel<<<gA, 256>>>(dmat, bmat, hmat, mask, domain);
    traj_kernel<<<BB, 512, SMEM_BYTES>>>(x, emb_W, emb_b, W_ih, W_hh, b_ih, b_hh,
                                         e2aW, e2ab, spaW, spab, a2eW, a2eb,
                                         clsW, clsb, h0, c0, out);
    (void)in_sizes; (void)n_in; (void)out_size;
}

// round 6
// speedup vs baseline: 1.3796x; 1.0606x over previous
#include <cuda_runtime.h>

// ---------------- problem constants ----------------
#define BB 128
#define NN 64
#define TT 20
#define FD 2
#define EE 16
#define HH 32
#define AA 32

// scratch for precomputed normalized attention weights: [B][T][N][N]
__device__ float g_wnorm[BB * TT * NN * NN];

typedef unsigned long long ull;

__device__ __forceinline__ ull ffma2(ull a, ull b, ull c) {
    ull d; asm("fma.rn.f32x2 %0, %1, %2, %3;" : "=l"(d) : "l"(a), "l"(b), "l"(c)); return d;
}
__device__ __forceinline__ ull pk2(float lo, float hi) {
    ull r; asm("mov.b64 %0, {%1, %2};" : "=l"(r) : "f"(lo), "f"(hi)); return r;
}
__device__ __forceinline__ float hadd2(ull v) {
    float lo, hi; asm("mov.b64 {%0, %1}, %2;" : "=f"(lo), "=f"(hi) : "l"(v)); return lo + hi;
}
__device__ __forceinline__ float ftanh_(float x) {
    float r; asm("tanh.approx.f32 %0, %1;" : "=f"(r) : "f"(x)); return r;
}
__device__ __forceinline__ float fsig(float x) {
    return fmaf(0.5f, ftanh_(0.5f * x), 0.5f);
}

// =====================================================================
// Kernel A: precompute normalized spatial attention weights for all (b,t)
// (unchanged — memory-bound, near roofline)
// =====================================================================
__global__ void __launch_bounds__(256) wnorm_kernel(
    const float* __restrict__ dmat, const float* __restrict__ bmat,
    const float* __restrict__ hmat, const float* __restrict__ mask,
    const float* __restrict__ domain)
{
    __shared__ float sdom[144];
    __shared__ float smk[NN];
    const int tt = blockIdx.x;
    const int b  = blockIdx.y;
    const int tid = threadIdx.x;
    if (tid < 144) sdom[tid] = domain[tid];
    if (tid < NN)  smk[tid]  = mask[(b * NN + tid) * TT + tt];
    __syncthreads();

    const int i = tid >> 2;
    const int q = tid & 3;
    const float mki = smk[i];
    const int base_in  = ((b * NN + i) * TT + tt) * NN + q * 16;
    const int base_out = ((b * TT + tt) * NN + i) * NN + q * 16;

    float wv[16];
    float psum = 0.0f;
#pragma unroll
    for (int u = 0; u < 4; u++) {
        float4 d4 = *(const float4*)(dmat + base_in + 4 * u);
        float4 b4 = *(const float4*)(bmat + base_in + 4 * u);
        float4 h4 = *(const float4*)(hmat + base_in + 4 * u);
        float dv[4] = {d4.x, d4.y, d4.z, d4.w};
        float bv[4] = {b4.x, b4.y, b4.z, b4.w};
        float hv[4] = {h4.x, h4.y, h4.z, h4.w};
#pragma unroll
        for (int v = 0; v < 4; v++) {
            int j = q * 16 + 4 * u + v;
            int ib = (int)floorf(bv[v] / 30.0f);
            int ih = (int)floorf(hv[v] / 30.0f);
            ib = ib < 0 ? 0 : (ib > 11 ? 11 : ib);
            ih = ih < 0 ? 0 : (ih > 11 ? 11 : ih);
            float val = sdom[ib * 12 + ih] - dv[v];
            val = val > 0.0f ? val : 0.0f;
            val *= mki * smk[j];
            if (j == i) val = 0.0f;
            wv[4 * u + v] = val;
            psum += val;
        }
    }
    psum += __shfl_xor_sync(0xffffffffu, psum, 1);
    psum += __shfl_xor_sync(0xffffffffu, psum, 2);
    const float inv = 1.0f / (psum + 1e-12f);
#pragma unroll
    for (int u = 0; u < 4; u++) {
        float4 o;
        o.x = wv[4 * u + 0] * inv;
        o.y = wv[4 * u + 1] * inv;
        o.z = wv[4 * u + 2] * inv;
        o.w = wv[4 * u + 3] * inv;
        *(float4*)(g_wnorm + base_out + 4 * u) = o;
    }
}

// =====================================================================
// Kernel B: sequential per-batch model. 1 CTA per batch, 256 threads.
// warp w (0..7) owns agents 8w..8w+7; lane l = output dim (0..31).
// f32x2 packed reductions; weight LDS amortized over 8 agents/warp.
// =====================================================================

// shared-memory layout (float offsets)
#define OFF_H    0        // [64][32]
#define OFF_HL   2048     // [64][32]
#define OFF_A    4096     // 2 x [64][32] (double-buffered)
#define OFF_ATT  8192     // [64][32]
#define OFF_Z    10240    // [64][32]
#define OFF_W    12288    // [8 warps][8 rows][64] attention weights (warp-private)
#define OFF_WH   16384    // W_hh staged k4-major: float4[8][128]
#define OFF_E2A  20480    // enc2att k4-major: float4[8][32]
#define OFF_SPA  21504    // spa_W  k4-major: float4[16][32]
#define OFF_A2E  23552    // att2enc k4-major: float4[8][32]
#define OFF_WC   24576    // combined x->gate weights: float2[128]
#define OFF_BC   24832    // combined gate bias: [128]
#define OFF_E2AB 24960    // [32]
#define OFF_SPAB 24992    // [32]
#define OFF_A2EB 25024    // [32]
#define OFF_X    25056    // [64][20][2]
#define SMEM_FLOATS 27616
#define SMEM_BYTES  (SMEM_FLOATS * 4)

__global__ void __launch_bounds__(256, 1) traj_kernel(
    const float* __restrict__ x,
    const float* __restrict__ emb_W,  const float* __restrict__ emb_b,
    const float* __restrict__ W_ih,   const float* __restrict__ W_hh,
    const float* __restrict__ b_ih,   const float* __restrict__ b_hh,
    const float* __restrict__ e2aW,   const float* __restrict__ e2ab,
    const float* __restrict__ spaW,   const float* __restrict__ spab,
    const float* __restrict__ a2eW,   const float* __restrict__ a2eb,
    const float* __restrict__ clsW,   const float* __restrict__ clsb,
    const float* __restrict__ h0,     const float* __restrict__ c0,
    float* __restrict__ out)
{
    extern __shared__ float sm[];
    const int b   = blockIdx.x;
    const int tid = threadIdx.x;
    const int w   = tid >> 5;   // 0..7
    const int l   = tid & 31;
    const int n0  = 8 * w;      // first agent of this warp

    float*  sh_h   = sm + OFF_H;
    float*  sh_hl  = sm + OFF_HL;
    float*  sh_a   = sm + OFF_A;
    float*  sh_att = sm + OFF_ATT;
    float*  sh_z   = sm + OFF_Z;
    float*  sh_x   = sm + OFF_X;
    float4* sh_h4  = (float4*)(sm + OFF_H);
    float4* shw4   = (float4*)(sm + OFF_W);
    float4* wh4f   = (float4*)(sm + OFF_WH);
    float4* e2a4f  = (float4*)(sm + OFF_E2A);
    float4* spa4f  = (float4*)(sm + OFF_SPA);
    float4* a2e4f  = (float4*)(sm + OFF_A2E);
    float2* wc2    = (float2*)(sm + OFF_WC);
    float*  bcA    = sm + OFF_BC;

    // packed-pair views
    const ulonglong2* wh2  = (const ulonglong2*)(sm + OFF_WH);
    const ulonglong2* e2a2 = (const ulonglong2*)(sm + OFF_E2A);
    const ulonglong2* spa2 = (const ulonglong2*)(sm + OFF_SPA);
    const ulonglong2* a2e2 = (const ulonglong2*)(sm + OFF_A2E);
    const ulonglong2* h2p   = (const ulonglong2*)(sm + OFF_H)   + n0 * 8;  // [agent][k4]
    const ulonglong2* hl2p  = (const ulonglong2*)(sm + OFF_HL)  + n0 * 8;
    const ulonglong2* att2p = (const ulonglong2*)(sm + OFF_ATT) + n0 * 8;
    const ulonglong2* z2p   = (const ulonglong2*)(sm + OFF_Z)   + n0 * 8;

    // ---------- prologue: stage weights & per-batch inputs ----------
    for (int idx = tid; idx < 1024; idx += 256) {
        int g = idx >> 3, k4 = idx & 7;
        wh4f[k4 * 128 + g] = ((const float4*)W_hh)[g * 8 + k4];
    }
    {
        int d = tid >> 3, k4 = tid & 7;
        e2a4f[k4 * 32 + d] = ((const float4*)e2aW)[d * 8 + k4];
        a2e4f[k4 * 32 + d] = ((const float4*)a2eW)[d * 8 + k4];
    }
    for (int idx = tid; idx < 512; idx += 256) {
        int d = idx >> 4, k4 = idx & 15;
        spa4f[k4 * 32 + d] = ((const float4*)spaW)[d * 16 + k4];
    }
    if (tid < 128) {
        float wc0 = 0.f, wc1 = 0.f, bcv = 0.f;
#pragma unroll
        for (int e = 0; e < EE; e++) {
            float we = W_ih[tid * EE + e];
            wc0 += we * emb_W[2 * e + 0];
            wc1 += we * emb_W[2 * e + 1];
            bcv += we * emb_b[e];
        }
        wc2[tid] = make_float2(wc0, wc1);
        bcA[tid] = bcv + b_ih[tid] + b_hh[tid];
    }
    if (tid >= 128 && tid < 160) {
        int t2 = tid - 128;
        sm[OFF_E2AB + t2] = e2ab[t2];
        sm[OFF_SPAB + t2] = spab[t2];
        sm[OFF_A2EB + t2] = a2eb[t2];
    }
    for (int idx = tid; idx < 640; idx += 256)
        ((float4*)sh_x)[idx] = ((const float4*)(x + (long)b * (NN * TT * FD)))[idx];
    for (int idx = tid; idx < 512; idx += 256)
        sh_h4[idx] = ((const float4*)(h0 + (long)b * (NN * HH)))[idx];
    __syncthreads();

    // c state in registers: thread owns (agent 8w+a, dim l)
    float creg[8];
#pragma unroll
    for (int a = 0; a < 8; a++)
        creg[a] = c0[(b * NN + n0 + a) * HH + l];

    // hoisted loop-invariant gate constants
    const float2 wci = wc2[l],      wcf = wc2[32 + l];
    const float2 wcg = wc2[64 + l], wco = wc2[96 + l];
    const float bci = bcA[l], bcf = bcA[32 + l], bcg = bcA[64 + l], bco = bcA[96 + l];
    const float e2abr = sm[OFF_E2AB + l];
    const float spabr = sm[OFF_SPAB + l];
    const float a2ebr = sm[OFF_A2EB + l];

    int buf = 0;

    for (int t = 0; t < TT; t++) {
        // ---- register prefetch of this warp's 8 attention-weight rows ----
        const float4* wsrc = (const float4*)(g_wnorm + ((long)b * TT + t) * (NN * NN) + w * 512);
        float4 wr0 = wsrc[l], wr1 = wsrc[l + 32], wr2 = wsrc[l + 64], wr3 = wsrc[l + 96];

        // ====== S1: LSTM gates + cell update (8 agents fused; weights loaded once/k4) ======
        {
            ull accI[8] = {0,0,0,0,0,0,0,0}, accF[8] = {0,0,0,0,0,0,0,0};
            ull accG[8] = {0,0,0,0,0,0,0,0}, accO[8] = {0,0,0,0,0,0,0,0};
#pragma unroll
            for (int k4 = 0; k4 < 8; k4++) {
                ulonglong2 wI = wh2[k4 * 128 + l];
                ulonglong2 wF = wh2[k4 * 128 + 32 + l];
                ulonglong2 wG = wh2[k4 * 128 + 64 + l];
                ulonglong2 wO = wh2[k4 * 128 + 96 + l];
#pragma unroll
                for (int a = 0; a < 8; a++) {
                    ulonglong2 hv = h2p[a * 8 + k4];
                    accI[a] = ffma2(hv.x, wI.x, accI[a]); accI[a] = ffma2(hv.y, wI.y, accI[a]);
                    accF[a] = ffma2(hv.x, wF.x, accF[a]); accF[a] = ffma2(hv.y, wF.y, accF[a]);
                    accG[a] = ffma2(hv.x, wG.x, accG[a]); accG[a] = ffma2(hv.y, wG.y, accG[a]);
                    accO[a] = ffma2(hv.x, wO.x, accO[a]); accO[a] = ffma2(hv.y, wO.y, accO[a]);
                }
            }
#pragma unroll
            for (int a = 0; a < 8; a++) {
                int n = n0 + a;
                float x0 = sh_x[n * (TT * FD) + 2 * t];
                float x1 = sh_x[n * (TT * FD) + 2 * t + 1];
                float gI = hadd2(accI[a]) + x0 * wci.x + x1 * wci.y + bci;
                float gF = hadd2(accF[a]) + x0 * wcf.x + x1 * wcf.y + bcf;
                float gG = hadd2(accG[a]) + x0 * wcg.x + x1 * wcg.y + bcg;
                float gO = hadd2(accO[a]) + x0 * wco.x + x1 * wco.y + bco;
                float cn = fsig(gF) * creg[a] + fsig(gI) * ftanh_(gG);
                creg[a] = cn;
                sh_hl[n * HH + l] = fsig(gO) * ftanh_(cn);
            }
        }
        __syncwarp();

        // ================= S2: a = hl @ enc2att_W^T + b =================
        {
            ull acc[8];
#pragma unroll
            for (int a = 0; a < 8; a++) acc[a] = pk2(e2abr, 0.0f);
#pragma unroll
            for (int k4 = 0; k4 < 8; k4++) {
                ulonglong2 wv = e2a2[k4 * 32 + l];
#pragma unroll
                for (int a = 0; a < 8; a++) {
                    ulonglong2 hv = hl2p[a * 8 + k4];
                    acc[a] = ffma2(hv.x, wv.x, acc[a]);
                    acc[a] = ffma2(hv.y, wv.y, acc[a]);
                }
            }
#pragma unroll
            for (int a = 0; a < 8; a++)
                sh_a[buf * 2048 + (n0 + a) * HH + l] = hadd2(acc[a]);
        }
        __syncthreads();   // publish sh_a[buf] to all warps (only block barrier per step)

        // ================= S3: att = w @ a (rows are warp-private) =================
        shw4[w * 128 + l]      = wr0;
        shw4[w * 128 + 32 + l] = wr1;
        shw4[w * 128 + 64 + l] = wr2;
        shw4[w * 128 + 96 + l] = wr3;
        __syncwarp();
        {
            const float* aB = sh_a + buf * 2048;
            const ulonglong2* wp2 = (const ulonglong2*)(shw4 + w * 128);
            ull acc[8] = {0, 0, 0, 0, 0, 0, 0, 0};
#pragma unroll
            for (int j4 = 0; j4 < 16; j4++) {
                float a0 = aB[(4 * j4 + 0) * HH + l];
                float a1 = aB[(4 * j4 + 1) * HH + l];
                float a2 = aB[(4 * j4 + 2) * HH + l];
                float a3 = aB[(4 * j4 + 3) * HH + l];
                ull ap0 = pk2(a0, a1);
                ull ap1 = pk2(a2, a3);
#pragma unroll
                for (int a = 0; a < 8; a++) {
                    ulonglong2 wv = wp2[a * 16 + j4];
                    acc[a] = ffma2(ap0, wv.x, acc[a]);
                    acc[a] = ffma2(ap1, wv.y, acc[a]);
                }
            }
#pragma unroll
            for (int a = 0; a < 8; a++)
                sh_att[(n0 + a) * HH + l] = hadd2(acc[a]);
        }
        __syncwarp();

        // ================= S4: z = tanh([a,att] @ spa_W^T + b) =================
        {
            const ulonglong2* a2p = (const ulonglong2*)(sh_a + buf * 2048) + n0 * 8;
            ull acc[8];
#pragma unroll
            for (int a = 0; a < 8; a++) acc[a] = pk2(spabr, 0.0f);
#pragma unroll
            for (int k4 = 0; k4 < 8; k4++) {
                ulonglong2 wv = spa2[k4 * 32 + l];
#pragma unroll
                for (int a = 0; a < 8; a++) {
                    ulonglong2 av = a2p[a * 8 + k4];
                    acc[a] = ffma2(av.x, wv.x, acc[a]);
                    acc[a] = ffma2(av.y, wv.y, acc[a]);
                }
            }
#pragma unroll
            for (int k4 = 0; k4 < 8; k4++) {
                ulonglong2 wv = spa2[(8 + k4) * 32 + l];
#pragma unroll
                for (int a = 0; a < 8; a++) {
                    ulonglong2 tv = att2p[a * 8 + k4];
                    acc[a] = ffma2(tv.x, wv.x, acc[a]);
                    acc[a] = ffma2(tv.y, wv.y, acc[a]);
                }
            }
#pragma unroll
            for (int a = 0; a < 8; a++)
                sh_z[(n0 + a) * HH + l] = ftanh_(hadd2(acc[a]));
        }
        __syncwarp();

        // ================= S5: h = z @ att2enc_W^T + b =================
        {
            ull acc[8];
#pragma unroll
            for (int a = 0; a < 8; a++) acc[a] = pk2(a2ebr, 0.0f);
#pragma unroll
            for (int k4 = 0; k4 < 8; k4++) {
                ulonglong2 wv = a2e2[k4 * 32 + l];
#pragma unroll
                for (int a = 0; a < 8; a++) {
                    ulonglong2 zv = z2p[a * 8 + k4];
                    acc[a] = ffma2(zv.x, wv.x, acc[a]);
                    acc[a] = ffma2(zv.y, wv.y, acc[a]);
                }
            }
#pragma unroll
            for (int a = 0; a < 8; a++)
                sh_h[(n0 + a) * HH + l] = hadd2(acc[a]);
        }
        __syncwarp();
        buf ^= 1;
    }

    // ================= classification: sigmoid(tanh(h @ cls_W^T + b)) =================
    const float cw  = clsW[l];
    const float cb0 = clsb[0];
#pragma unroll
    for (int a = 0; a < 8; a++) {
        int n = n0 + a;
        float v = sh_h[n * HH + l] * cw;
        v += __shfl_xor_sync(0xffffffffu, v, 16);
        v += __shfl_xor_sync(0xffffffffu, v, 8);
        v += __shfl_xor_sync(0xffffffffu, v, 4);
        v += __shfl_xor_sync(0xffffffffu, v, 2);
        v += __shfl_xor_sync(0xffffffffu, v, 1);
        if (l == 0) out[b * NN + n] = fsig(ftanh_(v + cb0));
    }
}

// =====================================================================
extern "C" void kernel_launch(void* const* d_in, const int* in_sizes, int n_in,
                              void* d_out, int out_size)
{
    const float* x      = (const float*)d_in[0];
    const float* dmat   = (const float*)d_in[1];
    const float* bmat   = (const float*)d_in[2];
    const float* hmat   = (const float*)d_in[3];
    const float* mask   = (const float*)d_in[4];
    const float* emb_W  = (const float*)d_in[5];
    const float* emb_b  = (const float*)d_in[6];
    const float* W_ih   = (const float*)d_in[7];
    const float* W_hh   = (const float*)d_in[8];
    const float* b_ih   = (const float*)d_in[9];
    const float* b_hh   = (const float*)d_in[10];
    const float* domain = (const float*)d_in[11];
    const float* e2aW   = (const float*)d_in[12];
    const float* e2ab   = (const float*)d_in[13];
    const float* spaW   = (const float*)d_in[14];
    const float* spab   = (const float*)d_in[15];
    const float* a2eW   = (const float*)d_in[16];
    const float* a2eb   = (const float*)d_in[17];
    const float* clsW   = (const float*)d_in[18];
    const float* clsb   = (const float*)d_in[19];
    const float* h0     = (const float*)d_in[20];
    const float* c0     = (const float*)d_in[21];
    float* out = (float*)d_out;

    cudaFuncSetAttribute(traj_kernel, cudaFuncAttributeMaxDynamicSharedMemorySize, SMEM_BYTES);

    dim3 gA(TT, BB);
    wnorm_kernel<<<gA, 256>>>(dmat, bmat, hmat, mask, domain);
    traj_kernel<<<BB, 256, SMEM_BYTES>>>(x, emb_W, emb_b, W_ih, W_hh, b_ih, b_hh,
                                         e2aW, e2ab, spaW, spab, a2eW, a2eb,
                                         clsW, clsb, h0, c0, out);
    (void)in_sizes; (void)n_in; (void)out_size;
}